// round 1
// baseline (speedup 1.0000x reference)
#include <cuda_runtime.h>

#define NV   4096
#define NSV  256
#define BB   2
#define GXD  128
#define GYD  128
#define GZD  16
#define CC   128
#define NCL  20
#define NH   8
#define DHD  16
#define NKW  256                   // 8192 keys / 32
#define MAPSZ (BB*GXD*GYD*GZD)     // 524288
#define EPSF 1e-5f

// ---------------- device scratch (no allocations allowed) ----------------
__device__ unsigned           g_flags[NKW];
__device__ int                g_rankbase[NKW];
__device__ int4               g_unq[NSV];         // (b, gx, gy, gz)
__device__ float              g_cf[NSV*CC];
__device__ float              g_hid[NSV*CC];
__device__ float              g_h[NSV*CC];
__device__ float              g_kT[CC*NSV];       // transposed K
__device__ float              g_v[NSV*CC];
__device__ float              g_q[NV*CC];
__device__ float              g_ctx[NV*CC];
__device__ float              g_y[NV*CC];
__device__ int                g_map[MAPSZ];
__device__ unsigned long long g_momi[9];
__device__ unsigned long long g_momu[9];
__device__ float              g_bnA[CC], g_bnD[CC];
__device__ float              g_pweff[4*64];      // w0,w1,w2,b' rows

// ---------------- init all mutable scratch (must run every launch) -------
__global__ void k_init() {
    int i = blockIdx.x * blockDim.x + threadIdx.x;
    if (i < MAPSZ)   g_map[i] = -1;
    if (i < NSV*CC)  g_cf[i] = 0.f;
    if (i < NKW)     g_flags[i] = 0u;
    if (i < 9)       g_momi[i] = 0ull;
}

// ---------------- keys -> bitmap, dense coord map, index moments ---------
__global__ void k_keys(const int* __restrict__ idx) {
    int n = blockIdx.x * 256 + threadIdx.x;
    int4 p = ((const int4*)idx)[n];
    int key = ((p.x * 32 + (p.y >> 2)) * 32 + (p.z >> 2)) * 4 + (p.w >> 2);
    atomicOr(&g_flags[key >> 5], 1u << (key & 31));
    g_map[((p.x * GXD + p.y) * GYD + p.z) * GZD + p.w] = n;

    long long xs = p.y, ys = p.z, zs = p.w;
    long long m[9] = { xs, ys, zs, xs*xs, ys*ys, zs*zs, xs*ys, xs*zs, ys*zs };
    __shared__ long long red[256];
    for (int k = 0; k < 9; k++) {
        red[threadIdx.x] = m[k];
        __syncthreads();
        for (int s = 128; s > 0; s >>= 1) {
            if (threadIdx.x < s) red[threadIdx.x] += red[threadIdx.x + s];
            __syncthreads();
        }
        if (threadIdx.x == 0) atomicAdd(&g_momi[k], (unsigned long long)red[0]);
        __syncthreads();
    }
}

// ---------------- bitmap scan -> ranks, sorted-unique coords, u-moments --
__global__ void k_unique() {
    int t = threadIdx.x;
    unsigned w = g_flags[t];
    int cnt = __popc(w);
    __shared__ int scan[256];
    scan[t] = cnt; __syncthreads();
    for (int off = 1; off < 256; off <<= 1) {
        int v = (t >= off) ? scan[t - off] : 0;
        __syncthreads();
        scan[t] += v;
        __syncthreads();
    }
    int excl = scan[t] - cnt;
    g_rankbase[t] = excl;
    unsigned wb = w;
    while (wb) {
        int bit = __ffs(wb) - 1; wb &= wb - 1;
        int rank = excl + __popc(w & ((1u << bit) - 1u));
        int key = t * 32 + bit;
        int4 u;
        u.w = key & 3;
        u.z = (key >> 2) & 31;
        u.y = (key >> 7) & 31;
        u.x = key >> 12;
        g_unq[rank] = u;
    }
    __syncthreads();
    int4 u = g_unq[t];
    long long xs = u.y, ys = u.z, zs = u.w;
    long long m[9] = { xs, ys, zs, xs*xs, ys*ys, zs*zs, xs*ys, xs*zs, ys*zs };
    __shared__ long long red[256];
    for (int k = 0; k < 9; k++) {
        red[t] = m[k]; __syncthreads();
        for (int s = 128; s > 0; s >>= 1) {
            if (t < s) red[t] += red[t + s];
            __syncthreads();
        }
        if (t == 0) g_momu[k] = (unsigned long long)red[0];
        __syncthreads();
    }
}

// ---------------- closed-form pbias BatchNorm fold ------------------------
__global__ void k_pprep(const float* __restrict__ pw1, const float* __restrict__ pb1,
                        const float* __restrict__ pg1, const float* __restrict__ pbe1) {
    __shared__ double md[3], Cv[3][3];
    if (threadIdx.x == 0) {
        double Si[9], Su[9];
        for (int k = 0; k < 9; k++) {
            Si[k] = (double)(long long)g_momi[k];
            Su[k] = (double)(long long)g_momu[k];
        }
        double mi[3], mu_[3];
        for (int a = 0; a < 3; a++) {
            mi[a]  = Si[a] / (double)NV;
            mu_[a] = Su[a] / (double)NSV;
            md[a]  = mi[a] - mu_[a];
        }
        const int pid[3][3] = { {3,6,7}, {6,4,8}, {7,8,5} };
        for (int a = 0; a < 3; a++)
            for (int b = 0; b < 3; b++)
                Cv[a][b] = (Si[pid[a][b]] / (double)NV  - mi[a]  * mi[b])
                         + (Su[pid[a][b]] / (double)NSV - mu_[a] * mu_[b]);
    }
    __syncthreads();
    int j = threadIdx.x;   // 64 threads
    double w[3];
    for (int a = 0; a < 3; a++) w[a] = (double)pw1[a*64 + j];
    double mu = md[0]*w[0] + md[1]*w[1] + md[2]*w[2] + (double)pb1[j];
    double var = 0.0;
    for (int a = 0; a < 3; a++)
        for (int b = 0; b < 3; b++)
            var += w[a] * Cv[a][b] * w[b];
    float s = rsqrtf((float)var + EPSF) * pg1[j];
    for (int a = 0; a < 3; a++) g_pweff[a*64 + j] = (float)w[a] * s;
    g_pweff[192 + j] = (float)((double)pb1[j] - mu) * s + pbe1[j];
}

// ---------------- per-voxel softmax + scatter to super-voxels -------------
__global__ void k_sms(const float* __restrict__ feat, const int* __restrict__ idx) {
    int n = blockIdx.x, t = threadIdx.x;
    float v = feat[n*CC + t];
    __shared__ float redm[4], reds[4];
    __shared__ int sinv;
    float m = v;
    for (int o = 16; o; o >>= 1) m = fmaxf(m, __shfl_xor_sync(~0u, m, o));
    if ((t & 31) == 0) redm[t >> 5] = m;
    __syncthreads();
    m = fmaxf(fmaxf(redm[0], redm[1]), fmaxf(redm[2], redm[3]));
    float e = expf(v - m);
    float s = e;
    for (int o = 16; o; o >>= 1) s += __shfl_xor_sync(~0u, s, o);
    if ((t & 31) == 0) reds[t >> 5] = s;
    if (t == 0) {
        int4 p = ((const int4*)idx)[n];
        int key = ((p.x * 32 + (p.y >> 2)) * 32 + (p.z >> 2)) * 4 + (p.w >> 2);
        sinv = g_rankbase[key >> 5] + __popc(g_flags[key >> 5] & ((1u << (key & 31)) - 1u));
    }
    __syncthreads();
    s = reds[0] + reds[1] + reds[2] + reds[3];
    atomicAdd(&g_cf[sinv*CC + t], e / s);
}

// ---------------- generic [rows,128] x [128,128] + bias -------------------
__global__ void k_gemm(const float* __restrict__ in, const float* __restrict__ W,
                       const float* __restrict__ bias, float* __restrict__ out,
                       int transOut) {
    int r = blockIdx.x, t = threadIdx.x;
    __shared__ float row[CC];
    row[t] = in[r*CC + t];
    __syncthreads();
    float acc = bias[t];
    #pragma unroll 8
    for (int k = 0; k < CC; k++) acc = fmaf(row[k], W[k*CC + t], acc);
    if (transOut) out[t*NSV + r] = acc;
    else          out[r*CC + t]  = acc;
}

// ---------------- BN stats (256 rows) for the cf MLP ----------------------
__global__ void k_bnstats(const float* __restrict__ g, const float* __restrict__ be) {
    int c = blockIdx.x, t = threadIdx.x;
    float x = g_hid[t*CC + c];
    float s = x, ss = x * x;
    for (int o = 16; o; o >>= 1) {
        s  += __shfl_xor_sync(~0u, s, o);
        ss += __shfl_xor_sync(~0u, ss, o);
    }
    __shared__ float rs[8], rss[8];
    if ((t & 31) == 0) { rs[t >> 5] = s; rss[t >> 5] = ss; }
    __syncthreads();
    if (t == 0) {
        float S = 0.f, SS = 0.f;
        for (int i = 0; i < 8; i++) { S += rs[i]; SS += rss[i]; }
        float mu = S / (float)NSV, var = SS / (float)NSV - mu * mu;
        float a = g[c] * rsqrtf(var + EPSF);
        g_bnA[c] = a;
        g_bnD[c] = be[c] - mu * a;
    }
}

__global__ void k_bnrelu() {
    int i = blockIdx.x * blockDim.x + threadIdx.x;   // 32768
    int c = i & (CC - 1);
    g_hid[i] = fmaxf(fmaf(g_hid[i], g_bnA[c], g_bnD[c]), 0.f);
}

// ---------------- fused cross-attention (scores + pbias + softmax + AV) ---
#define GQ 4
__global__ void __launch_bounds__(256, 4)
k_attn(const int* __restrict__ idx, const float* __restrict__ pw2,
       const float* __restrict__ pb2) {
    __shared__ float sq[GQ][CC];            // 2 KB
    __shared__ float sattn[GQ][NH][NSV];    // 32 KB
    __shared__ float spart[2][GQ][CC];      // 4 KB
    __shared__ float sw[4*64];              // 1 KB
    __shared__ float spw2[64];
    __shared__ float spos[GQ][3];
    int t = threadIdx.x;
    int n0 = blockIdx.x * GQ;

    if (t < 256) sw[t] = g_pweff[t];
    if (t < 64)  spw2[t] = pw2[t];
    if (t < GQ * 3) ((float*)spos)[t] = (float)idx[(n0 + t / 3) * 4 + 1 + (t % 3)];
    for (int i = t; i < GQ*CC; i += 256) ((float*)sq)[i] = g_q[n0*CC + i];
    __syncthreads();

    int s = t;                               // super-voxel id 0..255
    // pairwise position bias (BN folded)
    float pb[GQ];
    int4 u = g_unq[s];
    float pb2v = pb2[0];
    #pragma unroll
    for (int g = 0; g < GQ; g++) {
        float dx = spos[g][0] - (float)u.y;
        float dy = spos[g][1] - (float)u.z;
        float dz = spos[g][2] - (float)u.w;
        float acc = pb2v;
        #pragma unroll
        for (int j = 0; j < 64; j++) {
            float hh = fmaf(dx, sw[j], fmaf(dy, sw[64 + j], fmaf(dz, sw[128 + j], sw[192 + j])));
            acc = fmaf(fmaxf(hh, 0.f), spw2[j], acc);
        }
        pb[g] = acc;
    }
    // scores per head
    for (int h = 0; h < NH; h++) {
        float acc[GQ] = {0.f, 0.f, 0.f, 0.f};
        #pragma unroll
        for (int c16 = 0; c16 < DHD; c16++) {
            int c = h * DHD + c16;
            float kv = g_kT[c*NSV + s];
            #pragma unroll
            for (int g = 0; g < GQ; g++) acc[g] = fmaf(sq[g][c], kv, acc[g]);
        }
        #pragma unroll
        for (int g = 0; g < GQ; g++) sattn[g][h][s] = fmaf(acc[g], 0.25f, pb[g]);
    }
    __syncthreads();
    // softmax over s: 8 warps cover 32 (g,h) pairs
    int warp = t >> 5, lane = t & 31;
    for (int p = warp; p < GQ * NH; p += 8) {
        int g = p >> 3, h = p & 7;
        float vals[8];
        float m = -1e30f;
        #pragma unroll
        for (int k = 0; k < 8; k++) { vals[k] = sattn[g][h][lane + 32*k]; m = fmaxf(m, vals[k]); }
        for (int o = 16; o; o >>= 1) m = fmaxf(m, __shfl_xor_sync(~0u, m, o));
        float sum = 0.f;
        #pragma unroll
        for (int k = 0; k < 8; k++) { vals[k] = expf(vals[k] - m); sum += vals[k]; }
        for (int o = 16; o; o >>= 1) sum += __shfl_xor_sync(~0u, sum, o);
        float inv = 1.f / sum;
        #pragma unroll
        for (int k = 0; k < 8; k++) sattn[g][h][lane + 32*k] = vals[k] * inv;
    }
    __syncthreads();
    // attn @ V
    int c = t & (CC - 1), half = t >> 7;
    int hh = c >> 4;
    float acc[GQ] = {0.f, 0.f, 0.f, 0.f};
    for (int sI = half * 128; sI < half * 128 + 128; sI++) {
        float vv = g_v[sI*CC + c];
        #pragma unroll
        for (int g = 0; g < GQ; g++) acc[g] = fmaf(sattn[g][hh][sI], vv, acc[g]);
    }
    #pragma unroll
    for (int g = 0; g < GQ; g++) spart[half][g][c] = acc[g];
    __syncthreads();
    if (half == 0) {
        #pragma unroll
        for (int g = 0; g < GQ; g++)
            g_ctx[(n0 + g)*CC + c] = spart[0][g][c] + spart[1][g][c];
    }
}

// ---------------- o-projection + residual + LayerNorm ---------------------
__global__ void k_outln(const float* __restrict__ feat, const float* __restrict__ wo,
                        const float* __restrict__ bo, const float* __restrict__ lg,
                        const float* __restrict__ lb) {
    int n = blockIdx.x, t = threadIdx.x;
    __shared__ float row[CC];
    row[t] = g_ctx[n*CC + t];
    __syncthreads();
    float acc = bo[t];
    #pragma unroll 8
    for (int k = 0; k < CC; k++) acc = fmaf(row[k], wo[k*CC + t], acc);
    float y = feat[n*CC + t] + acc;
    float s = y, ss = y * y;
    for (int o = 16; o; o >>= 1) {
        s  += __shfl_xor_sync(~0u, s, o);
        ss += __shfl_xor_sync(~0u, ss, o);
    }
    __shared__ float rs[4], rss[4];
    if ((t & 31) == 0) { rs[t >> 5] = s; rss[t >> 5] = ss; }
    __syncthreads();
    s  = rs[0] + rs[1] + rs[2] + rs[3];
    ss = rss[0] + rss[1] + rss[2] + rss[3];
    float mu = s / (float)CC, var = ss / (float)CC - mu * mu;
    g_y[n*CC + t] = (y - mu) * rsqrtf(var + EPSF) * lg[t] + lb[t];
}

// ---------------- submanifold 3^3 conv via neighbor gather ----------------
__global__ void __launch_bounds__(320, 4)
k_conv(const int* __restrict__ idx, const float* __restrict__ segw,
       const float* __restrict__ segb, float* __restrict__ out) {
    __shared__ float sW[CC*NCL];   // 10 KB
    __shared__ int4 svox[16];
    int t = threadIdx.x;
    int n0 = blockIdx.x * 16;
    if (t < 16) svox[t] = ((const int4*)idx)[n0 + t];
    __syncthreads();
    int v = t / NCL, oc = t % NCL;   // 16 voxels x 20 outputs
    int4 pv = svox[v];
    float acc = segb[oc];
    for (int d = 0; d < 27; d++) {
        for (int i = t; i < CC*NCL; i += 320) sW[i] = segw[d*CC*NCL + i];
        __syncthreads();
        int ax = d / 9, ay = (d / 3) % 3, az = d % 3;
        int x = pv.y + ax - 1, y = pv.z + ay - 1, z = pv.w + az - 1;
        if (x >= 0 && x < GXD && y >= 0 && y < GYD && z >= 0 && z < GZD) {
            int m = g_map[((pv.x * GXD + x) * GYD + y) * GZD + z];
            if (m >= 0) {
                const float* yr = &g_y[m*CC];
                #pragma unroll 8
                for (int c2 = 0; c2 < CC; c2++) acc = fmaf(yr[c2], sW[c2*NCL + oc], acc);
            }
        }
        __syncthreads();
    }
    out[(n0 + v)*NCL + oc] = acc;
}

// --------------------------------------------------------------------------
extern "C" void kernel_launch(void* const* d_in, const int* in_sizes, int n_in,
                              void* d_out, int out_size) {
    const int*   idx  = (const int*)  d_in[0];
    const float* feat = (const float*)d_in[1];
    const float* cw1  = (const float*)d_in[2];
    const float* cb1  = (const float*)d_in[3];
    const float* cg1  = (const float*)d_in[4];
    const float* cbe1 = (const float*)d_in[5];
    const float* cw2  = (const float*)d_in[6];
    const float* cb2  = (const float*)d_in[7];
    const float* pw1  = (const float*)d_in[8];
    const float* pb1  = (const float*)d_in[9];
    const float* pg1  = (const float*)d_in[10];
    const float* pbe1 = (const float*)d_in[11];
    const float* pw2  = (const float*)d_in[12];
    const float* pb2  = (const float*)d_in[13];
    const float* wq   = (const float*)d_in[14];
    const float* bq   = (const float*)d_in[15];
    const float* wk   = (const float*)d_in[16];
    const float* bk   = (const float*)d_in[17];
    const float* wv   = (const float*)d_in[18];
    const float* bv   = (const float*)d_in[19];
    const float* wo   = (const float*)d_in[20];
    const float* bo   = (const float*)d_in[21];
    const float* ln_g = (const float*)d_in[22];
    const float* ln_b = (const float*)d_in[23];
    const float* segw = (const float*)d_in[24];
    const float* segb = (const float*)d_in[25];

    void *p_cf, *p_hid, *p_h, *p_kT, *p_v, *p_q;
    cudaGetSymbolAddress(&p_cf,  g_cf);
    cudaGetSymbolAddress(&p_hid, g_hid);
    cudaGetSymbolAddress(&p_h,   g_h);
    cudaGetSymbolAddress(&p_kT,  g_kT);
    cudaGetSymbolAddress(&p_v,   g_v);
    cudaGetSymbolAddress(&p_q,   g_q);

    k_init   <<<MAPSZ/256, 256>>>();
    k_keys   <<<NV/256, 256>>>(idx);
    k_unique <<<1, 256>>>();
    k_pprep  <<<1, 64>>>(pw1, pb1, pg1, pbe1);
    k_sms    <<<NV, 128>>>(feat, idx);

    k_gemm   <<<NSV, 128>>>((const float*)p_cf, cw1, cb1, (float*)p_hid, 0);
    k_bnstats<<<CC, 256>>>(cg1, cbe1);
    k_bnrelu <<<128, 256>>>();
    k_gemm   <<<NSV, 128>>>((const float*)p_hid, cw2, cb2, (float*)p_h, 0);

    k_gemm   <<<NSV, 128>>>((const float*)p_h, wk, bk, (float*)p_kT, 1);
    k_gemm   <<<NSV, 128>>>((const float*)p_h, wv, bv, (float*)p_v, 0);
    k_gemm   <<<NV,  128>>>(feat, wq, bq, (float*)p_q, 0);

    k_attn   <<<NV/GQ, 256>>>(idx, pw2, pb2);
    k_outln  <<<NV, 128>>>(feat, wo, bo, ln_g, ln_b);
    k_conv   <<<NV/16, 320>>>(idx, segw, segb, (float*)d_out);
}

// round 2
// speedup vs baseline: 1.4244x; 1.4244x over previous
#include <cuda_runtime.h>

#define NV   4096
#define NSV  256
#define BB   2
#define GXD  128
#define GYD  128
#define GZD  16
#define CC   128
#define NCL  20
#define NH   8
#define DHD  16
#define NKW  256                   // 8192 keys / 32
#define MAPSZ (BB*GXD*GYD*GZD)     // 524288
#define EPSF 1e-5f
#define GQ   8

// ---------------- device scratch ----------------
__device__ unsigned           g_flags[NKW];
__device__ int                g_rankbase[NKW];
__device__ int4               g_unq[NSV];
__device__ float              g_cf[NSV*CC];
__device__ float              g_hid[NSV*CC];
__device__ float              g_h[NSV*CC];
__device__ float              g_kT[CC*NSV];       // transposed K
__device__ float              g_v[NSV*CC];
__device__ float              g_y[NV*CC];
__device__ int                g_map[MAPSZ];
__device__ unsigned long long g_momi[9];
__device__ float              g_bnA[CC], g_bnD[CC];
__device__ float              g_pweff[4*64];

// ---------------- keys -> bitmap, dense coord map, index moments ---------
__global__ void k_keys(const int* __restrict__ idx) {
    int n = blockIdx.x * 256 + threadIdx.x;
    int lane = threadIdx.x & 31;
    int4 p = ((const int4*)idx)[n];
    int key = ((p.x * 32 + (p.y >> 2)) * 32 + (p.z >> 2)) * 4 + (p.w >> 2);
    atomicOr(&g_flags[key >> 5], 1u << (key & 31));
    g_map[((p.x * GXD + p.y) * GYD + p.z) * GZD + p.w] = n;

    long long xs = p.y, ys = p.z, zs = p.w;
    long long m[9] = { xs, ys, zs, xs*xs, ys*ys, zs*zs, xs*ys, xs*zs, ys*zs };
    #pragma unroll
    for (int k = 0; k < 9; k++) {
        long long v = m[k];
        for (int o = 16; o; o >>= 1) v += __shfl_xor_sync(~0u, v, o);
        if (lane == 0) atomicAdd(&g_momi[k], (unsigned long long)v);
    }
}

// ---------------- bitmap scan -> unique + closed-form pbias BN fold ------
__global__ void k_unique(const float* __restrict__ pw1, const float* __restrict__ pb1,
                         const float* __restrict__ pg1, const float* __restrict__ pbe1) {
    int t = threadIdx.x;
    unsigned w = g_flags[t];
    int cnt = __popc(w);
    __shared__ int scan[256];
    scan[t] = cnt; __syncthreads();
    for (int off = 1; off < 256; off <<= 1) {
        int v = (t >= off) ? scan[t - off] : 0;
        __syncthreads();
        scan[t] += v;
        __syncthreads();
    }
    int excl = scan[t] - cnt;
    g_rankbase[t] = excl;
    unsigned wb = w;
    while (wb) {
        int bit = __ffs(wb) - 1; wb &= wb - 1;
        int rank = excl + __popc(w & ((1u << bit) - 1u));
        int key = t * 32 + bit;
        int4 u;
        u.w = key & 3;
        u.z = (key >> 2) & 31;
        u.y = (key >> 7) & 31;
        u.x = key >> 12;
        g_unq[rank] = u;
    }
    __syncthreads();
    // super-voxel coordinate moments
    __shared__ double Su[9];
    {
        int4 u = g_unq[t];
        long long xs = u.y, ys = u.z, zs = u.w;
        long long m[9] = { xs, ys, zs, xs*xs, ys*ys, zs*zs, xs*ys, xs*zs, ys*zs };
        __shared__ long long red[256];
        for (int k = 0; k < 9; k++) {
            red[t] = m[k]; __syncthreads();
            for (int s = 128; s > 0; s >>= 1) {
                if (t < s) red[t] += red[t + s];
                __syncthreads();
            }
            if (t == 0) Su[k] = (double)red[0];
            __syncthreads();
        }
    }
    // closed-form BatchNorm fold for the pairwise pos-bias MLP
    __shared__ double md[3], Cv[3][3];
    if (t == 0) {
        double Si[9];
        for (int k = 0; k < 9; k++) Si[k] = (double)(long long)g_momi[k];
        double mi[3], mu_[3];
        for (int a = 0; a < 3; a++) {
            mi[a]  = Si[a] / (double)NV;
            mu_[a] = Su[a] / (double)NSV;
            md[a]  = mi[a] - mu_[a];
        }
        const int pid[3][3] = { {3,6,7}, {6,4,8}, {7,8,5} };
        for (int a = 0; a < 3; a++)
            for (int b = 0; b < 3; b++)
                Cv[a][b] = (Si[pid[a][b]] / (double)NV  - mi[a]  * mi[b])
                         + (Su[pid[a][b]] / (double)NSV - mu_[a] * mu_[b]);
    }
    __syncthreads();
    if (t < 64) {
        int j = t;
        double w3[3];
        for (int a = 0; a < 3; a++) w3[a] = (double)pw1[a*64 + j];
        double mu = md[0]*w3[0] + md[1]*w3[1] + md[2]*w3[2] + (double)pb1[j];
        double var = 0.0;
        for (int a = 0; a < 3; a++)
            for (int b = 0; b < 3; b++)
                var += w3[a] * Cv[a][b] * w3[b];
        float s = rsqrtf((float)var + EPSF) * pg1[j];
        for (int a = 0; a < 3; a++) g_pweff[a*64 + j] = (float)w3[a] * s;
        g_pweff[192 + j] = (float)((double)pb1[j] - mu) * s + pbe1[j];
    }
}

// ---------------- per-voxel softmax + scatter to super-voxels -------------
__global__ void k_sms(const float* __restrict__ feat, const int* __restrict__ idx) {
    int n = blockIdx.x, t = threadIdx.x;
    float v = feat[n*CC + t];
    __shared__ float redm[4], reds[4];
    __shared__ int sinv;
    float m = v;
    for (int o = 16; o; o >>= 1) m = fmaxf(m, __shfl_xor_sync(~0u, m, o));
    if ((t & 31) == 0) redm[t >> 5] = m;
    __syncthreads();
    m = fmaxf(fmaxf(redm[0], redm[1]), fmaxf(redm[2], redm[3]));
    float e = expf(v - m);
    float s = e;
    for (int o = 16; o; o >>= 1) s += __shfl_xor_sync(~0u, s, o);
    if ((t & 31) == 0) reds[t >> 5] = s;
    if (t == 0) {
        int4 p = ((const int4*)idx)[n];
        int key = ((p.x * 32 + (p.y >> 2)) * 32 + (p.z >> 2)) * 4 + (p.w >> 2);
        sinv = g_rankbase[key >> 5] + __popc(g_flags[key >> 5] & ((1u << (key & 31)) - 1u));
    }
    __syncthreads();
    s = reds[0] + reds[1] + reds[2] + reds[3];
    atomicAdd(&g_cf[sinv*CC + t], e / s);
}

// ---------------- [256,128] x [128,128] + bias -----------------------------
__global__ void k_gemm(const float* __restrict__ in, const float* __restrict__ W,
                       const float* __restrict__ bias, float* __restrict__ out) {
    int r = blockIdx.x, t = threadIdx.x;
    __shared__ float row[CC];
    row[t] = in[r*CC + t];
    __syncthreads();
    float acc = bias[t];
    #pragma unroll 8
    for (int k = 0; k < CC; k++) acc = fmaf(row[k], W[k*CC + t], acc);
    out[r*CC + t] = acc;
}

// input row passes through BN+ReLU (stats in g_bnA/g_bnD)
__global__ void k_gemm_bn(const float* __restrict__ W, const float* __restrict__ bias,
                          float* __restrict__ out) {
    int r = blockIdx.x, t = threadIdx.x;
    __shared__ float row[CC];
    row[t] = fmaxf(fmaf(g_hid[r*CC + t], g_bnA[t], g_bnD[t]), 0.f);
    __syncthreads();
    float acc = bias[t];
    #pragma unroll 8
    for (int k = 0; k < CC; k++) acc = fmaf(row[k], W[k*CC + t], acc);
    out[r*CC + t] = acc;
}

// fused K (transposed out) + V projections: 512 blocks
__global__ void k_gemmkv(const float* __restrict__ wk, const float* __restrict__ bk,
                         const float* __restrict__ wv, const float* __restrict__ bv) {
    int b = blockIdx.x;
    int r = b & (NSV - 1), t = threadIdx.x;
    __shared__ float row[CC];
    row[t] = g_h[r*CC + t];
    __syncthreads();
    const float* W    = (b < NSV) ? wk : wv;
    const float* bias = (b < NSV) ? bk : bv;
    float acc = bias[t];
    #pragma unroll 8
    for (int k = 0; k < CC; k++) acc = fmaf(row[k], W[k*CC + t], acc);
    if (b < NSV) g_kT[t*NSV + r] = acc;
    else         g_v[r*CC + t]   = acc;
}

// ---------------- BN stats over 256 rows ----------------------------------
__global__ void k_bnstats(const float* __restrict__ g, const float* __restrict__ be) {
    int c = blockIdx.x, t = threadIdx.x;
    float x = g_hid[t*CC + c];
    float s = x, ss = x * x;
    for (int o = 16; o; o >>= 1) {
        s  += __shfl_xor_sync(~0u, s, o);
        ss += __shfl_xor_sync(~0u, ss, o);
    }
    __shared__ float rs[8], rss[8];
    if ((t & 31) == 0) { rs[t >> 5] = s; rss[t >> 5] = ss; }
    __syncthreads();
    if (t == 0) {
        float S = 0.f, SS = 0.f;
        for (int i = 0; i < 8; i++) { S += rs[i]; SS += rss[i]; }
        float mu = S / (float)NSV, var = SS / (float)NSV - mu * mu;
        float a = g[c] * rsqrtf(var + EPSF);
        g_bnA[c] = a;
        g_bnD[c] = be[c] - mu * a;
    }
}

// ---------------- fully fused attention ------------------------------------
// q-proj + pbias + scores + softmax + AV + o-proj + residual + LayerNorm
__global__ void __launch_bounds__(256, 2)
k_attn(const int* __restrict__ idx, const float* __restrict__ feat,
       const float* __restrict__ wq, const float* __restrict__ bq,
       const float* __restrict__ wo, const float* __restrict__ bo,
       const float* __restrict__ lng, const float* __restrict__ lnb,
       const float* __restrict__ pw2, const float* __restrict__ pb2) {
    extern __shared__ float sm[];
    float* sfeat = sm;                              // 8*128
    float* sq    = sm + GQ*CC;                      // 8*128
    float* satt  = sm + 2*GQ*CC;                    // 8*8*256
    float* sctx  = satt + GQ*NH*NSV;                // 8*128
    float* sw    = sctx + GQ*CC;                    // 256
    float* spw2  = sw + 256;                        // 64
    float* spos  = spw2 + 64;                       // 24
    float* sred  = spos + 24;                       // 64 (LN partials)

    int t = threadIdx.x;
    int n0 = blockIdx.x * GQ;
    int c = t & (CC - 1), grp = t >> 7, g0 = grp * 4;

    sw[t] = g_pweff[t];
    if (t < 64) spw2[t] = pw2[t];
    if (t < GQ * 3) spos[t] = (float)idx[(n0 + t / 3) * 4 + 1 + (t % 3)];
    #pragma unroll
    for (int i = 0; i < GQ*CC/256; i++)
        sfeat[t + 256*i] = feat[n0*CC + t + 256*i];
    __syncthreads();

    // ---- q projection (scale 1/sqrt(DH)=0.25 folded in) ----
    {
        float acc[4];
        float bqc = bq[c] ;
        #pragma unroll
        for (int gg = 0; gg < 4; gg++) acc[gg] = bqc;
        #pragma unroll 4
        for (int k = 0; k < CC; k++) {
            float w = wq[k*CC + c];
            #pragma unroll
            for (int gg = 0; gg < 4; gg++)
                acc[gg] = fmaf(sfeat[(g0+gg)*CC + k], w, acc[gg]);
        }
        #pragma unroll
        for (int gg = 0; gg < 4; gg++) sq[(g0+gg)*CC + c] = acc[gg] * 0.25f;
    }
    __syncthreads();

    // ---- pbias (BN folded, closed form) + scores: thread = super-voxel s ----
    {
        int s = t;
        int4 u = g_unq[s];
        float pb[GQ];
        float pb2v = pb2[0];
        float ux = (float)u.y, uy = (float)u.z, uz = (float)u.w;
        #pragma unroll
        for (int g = 0; g < GQ; g++) {
            float dx = spos[g*3+0] - ux;
            float dy = spos[g*3+1] - uy;
            float dz = spos[g*3+2] - uz;
            float acc = pb2v;
            #pragma unroll
            for (int j = 0; j < 64; j++) {
                float hh = fmaf(dx, sw[j], fmaf(dy, sw[64+j], fmaf(dz, sw[128+j], sw[192+j])));
                acc = fmaf(fmaxf(hh, 0.f), spw2[j], acc);
            }
            pb[g] = acc;
        }
        for (int h = 0; h < NH; h++) {
            float acc[GQ];
            #pragma unroll
            for (int g = 0; g < GQ; g++) acc[g] = pb[g];
            #pragma unroll
            for (int c16 = 0; c16 < DHD; c16++) {
                int cc = h * DHD + c16;
                float kv = g_kT[cc*NSV + s];
                #pragma unroll
                for (int g = 0; g < GQ; g++) acc[g] = fmaf(sq[g*CC + cc], kv, acc[g]);
            }
            #pragma unroll
            for (int g = 0; g < GQ; g++) satt[(g*NH + h)*NSV + s] = acc[g];
        }
    }
    __syncthreads();

    // ---- softmax over s: 8 warps cover 64 (g,h) pairs ----
    {
        int warp = t >> 5, lane = t & 31;
        for (int p = warp; p < GQ * NH; p += 8) {
            float* row = &satt[p * NSV];
            float vals[8];
            float m = -1e30f;
            #pragma unroll
            for (int k = 0; k < 8; k++) { vals[k] = row[lane + 32*k]; m = fmaxf(m, vals[k]); }
            for (int o = 16; o; o >>= 1) m = fmaxf(m, __shfl_xor_sync(~0u, m, o));
            float sum = 0.f;
            #pragma unroll
            for (int k = 0; k < 8; k++) { vals[k] = expf(vals[k] - m); sum += vals[k]; }
            for (int o = 16; o; o >>= 1) sum += __shfl_xor_sync(~0u, sum, o);
            float inv = 1.f / sum;
            #pragma unroll
            for (int k = 0; k < 8; k++) row[lane + 32*k] = vals[k] * inv;
        }
    }
    __syncthreads();

    // ---- attn @ V: thread (c, grp) accumulates 4 rows over all 256 s ----
    {
        int hh = c >> 4;
        float acc[4] = {0.f, 0.f, 0.f, 0.f};
        for (int s = 0; s < NSV; s++) {
            float vv = g_v[s*CC + c];
            #pragma unroll
            for (int gg = 0; gg < 4; gg++)
                acc[gg] = fmaf(satt[((g0+gg)*NH + hh)*NSV + s], vv, acc[gg]);
        }
        #pragma unroll
        for (int gg = 0; gg < 4; gg++) sctx[(g0+gg)*CC + c] = acc[gg];
    }
    __syncthreads();

    // ---- o-proj + residual + LayerNorm ----
    {
        float acc[4];
        float boc = bo[c];
        #pragma unroll
        for (int gg = 0; gg < 4; gg++) acc[gg] = boc;
        #pragma unroll 4
        for (int k = 0; k < CC; k++) {
            float w = wo[k*CC + c];
            #pragma unroll
            for (int gg = 0; gg < 4; gg++)
                acc[gg] = fmaf(sctx[(g0+gg)*CC + k], w, acc[gg]);
        }
        float yv[4];
        #pragma unroll
        for (int gg = 0; gg < 4; gg++) yv[gg] = sfeat[(g0+gg)*CC + c] + acc[gg];

        int warp = t >> 5, lane = t & 31, w4 = warp & 3;
        #pragma unroll
        for (int gg = 0; gg < 4; gg++) {
            float s = yv[gg], ss = yv[gg] * yv[gg];
            for (int o = 16; o; o >>= 1) {
                s  += __shfl_xor_sync(~0u, s, o);
                ss += __shfl_xor_sync(~0u, ss, o);
            }
            if (lane == 0) {
                sred[(g0+gg)*4 + w4]      = s;
                sred[32 + (g0+gg)*4 + w4] = ss;
            }
        }
        __syncthreads();
        float lg = lng[c], lb = lnb[c];
        #pragma unroll
        for (int gg = 0; gg < 4; gg++) {
            int g = g0 + gg;
            float s  = sred[g*4+0] + sred[g*4+1] + sred[g*4+2] + sred[g*4+3];
            float ss = sred[32+g*4+0] + sred[32+g*4+1] + sred[32+g*4+2] + sred[32+g*4+3];
            float mu = s * (1.f/CC), var = ss * (1.f/CC) - mu * mu;
            g_y[(n0+g)*CC + c] = (yv[gg] - mu) * rsqrtf(var + EPSF) * lg + lb;
        }
    }
}

// ---------------- submanifold 3^3 conv: 32 voxels/block --------------------
__global__ void __launch_bounds__(640, 2)
k_conv(const int* __restrict__ idx, const float* __restrict__ segw,
       const float* __restrict__ segb, float* __restrict__ out) {
    __shared__ float sW[CC*NCL];   // 10 KB
    __shared__ int4 svox[32];
    int t = threadIdx.x;
    int n0 = blockIdx.x * 32;
    if (t < 32) svox[t] = ((const int4*)idx)[n0 + t];
    __syncthreads();
    int v = t / NCL, oc = t - v * NCL;   // 32 voxels x 20 outputs
    int4 pv = svox[v];
    float acc = segb[oc];
    for (int d = 0; d < 27; d++) {
        for (int i = t; i < CC*NCL; i += 640) sW[i] = segw[d*CC*NCL + i];
        __syncthreads();
        int ax = d / 9, ay = (d / 3) % 3, az = d % 3;
        int x = pv.y + ax - 1, y = pv.z + ay - 1, z = pv.w + az - 1;
        if (x >= 0 && x < GXD && y >= 0 && y < GYD && z >= 0 && z < GZD) {
            int m = g_map[((pv.x * GXD + x) * GYD + y) * GZD + z];
            if (m >= 0) {
                const float* yr = &g_y[m*CC];
                #pragma unroll 8
                for (int c2 = 0; c2 < CC; c2++) acc = fmaf(yr[c2], sW[c2*NCL + oc], acc);
            }
        }
        __syncthreads();
    }
    out[(n0 + v)*NCL + oc] = acc;
}

// --------------------------------------------------------------------------
extern "C" void kernel_launch(void* const* d_in, const int* in_sizes, int n_in,
                              void* d_out, int out_size) {
    const int*   idx  = (const int*)  d_in[0];
    const float* feat = (const float*)d_in[1];
    const float* cw1  = (const float*)d_in[2];
    const float* cb1  = (const float*)d_in[3];
    const float* cg1  = (const float*)d_in[4];
    const float* cbe1 = (const float*)d_in[5];
    const float* cw2  = (const float*)d_in[6];
    const float* cb2  = (const float*)d_in[7];
    const float* pw1  = (const float*)d_in[8];
    const float* pb1  = (const float*)d_in[9];
    const float* pg1  = (const float*)d_in[10];
    const float* pbe1 = (const float*)d_in[11];
    const float* pw2  = (const float*)d_in[12];
    const float* pb2  = (const float*)d_in[13];
    const float* wq   = (const float*)d_in[14];
    const float* bq   = (const float*)d_in[15];
    const float* wk   = (const float*)d_in[16];
    const float* bk   = (const float*)d_in[17];
    const float* wv   = (const float*)d_in[18];
    const float* bv   = (const float*)d_in[19];
    const float* wo   = (const float*)d_in[20];
    const float* bo   = (const float*)d_in[21];
    const float* ln_g = (const float*)d_in[22];
    const float* ln_b = (const float*)d_in[23];
    const float* segw = (const float*)d_in[24];
    const float* segb = (const float*)d_in[25];

    void *p_cf, *p_hid, *p_h, *p_map, *p_flags, *p_momi;
    cudaGetSymbolAddress(&p_cf,    g_cf);
    cudaGetSymbolAddress(&p_hid,   g_hid);
    cudaGetSymbolAddress(&p_h,     g_h);
    cudaGetSymbolAddress(&p_map,   g_map);
    cudaGetSymbolAddress(&p_flags, g_flags);
    cudaGetSymbolAddress(&p_momi,  g_momi);

    constexpr int ATTN_SMEM = (2*GQ*CC + GQ*NH*NSV + GQ*CC + 256 + 64 + 24 + 64) * 4;
    cudaFuncSetAttribute(k_attn, cudaFuncAttributeMaxDynamicSharedMemorySize, ATTN_SMEM);

    cudaMemsetAsync(p_map,   0xFF, MAPSZ * sizeof(int), 0);
    cudaMemsetAsync(p_flags, 0,    NKW * sizeof(unsigned), 0);
    cudaMemsetAsync(p_cf,    0,    NSV * CC * sizeof(float), 0);
    cudaMemsetAsync(p_momi,  0,    9 * sizeof(unsigned long long), 0);

    k_keys   <<<NV/256, 256>>>(idx);
    k_unique <<<1, 256>>>(pw1, pb1, pg1, pbe1);
    k_sms    <<<NV, 128>>>(feat, idx);

    k_gemm   <<<NSV, 128>>>((const float*)p_cf, cw1, cb1, (float*)p_hid);
    k_bnstats<<<CC, 256>>>(cg1, cbe1);
    k_gemm_bn<<<NSV, 128>>>(cw2, cb2, (float*)p_h);
    k_gemmkv <<<2*NSV, 128>>>(wk, bk, wv, bv);

    k_attn   <<<NV/GQ, 256, ATTN_SMEM>>>(idx, feat, wq, bq, wo, bo, ln_g, ln_b, pw2, pb2);
    k_conv   <<<NV/32, 640>>>(idx, segw, segb, (float*)d_out);
}

// round 3
// speedup vs baseline: 2.0339x; 1.4279x over previous
#include <cuda_runtime.h>

#define NV   4096
#define NSV  256
#define BB   2
#define GXD  128
#define GYD  128
#define GZD  16
#define CC   128
#define NCL  20
#define NH   8
#define DHD  16
#define MAPSZ (BB*GXD*GYD*GZD)
#define EPSF 1e-5f
#define GQ   8

// ---------------- packed f32x2 helpers ----------------
typedef unsigned long long ull;
__device__ __forceinline__ ull pk(float lo, float hi) {
    ull r; asm("mov.b64 %0, {%1,%2};" : "=l"(r) : "f"(lo), "f"(hi)); return r;
}
__device__ __forceinline__ ull pk2(float2 f) { return pk(f.x, f.y); }
__device__ __forceinline__ void upk(float& lo, float& hi, ull v) {
    asm("mov.b64 {%0,%1}, %2;" : "=f"(lo), "=f"(hi) : "l"(v));
}
#define FMA2(d,a,b,c) asm("fma.rn.f32x2 %0, %1, %2, %3;" : "=l"(d) : "l"(a), "l"(b), "l"(c))

// ---------------- device scratch ----------------
struct Acc { float cf[NSV*CC]; float s1[CC]; float s2[CC]; };
__device__ Acc  g_acc;
__device__ int4 g_unq[NSV];
__device__ int  g_sinv[NV];
__device__ float g_hid[NSV*CC];
__device__ float g_kT[CC*NSV];
__device__ float g_v[NSV*CC];
__device__ float g_y[NV*CC];
__device__ int   g_map[MAPSZ];          // zero-init; stores n+1
__device__ float g_pweff[4*64];

// ================= k_prep: keys, unique, inverse, pbias BN fold ==========
__global__ void k_prep(const int* __restrict__ idx,
                       const float* __restrict__ pw1, const float* __restrict__ pb1,
                       const float* __restrict__ pg1, const float* __restrict__ pbe1) {
    __shared__ unsigned sflags[256];
    __shared__ unsigned short skeys[NV];
    __shared__ int sscan[256], srank[256];
    __shared__ long long wred[8];
    __shared__ double Si[9], Su[9], md[3], Cv[3][3];
    int t = threadIdx.x, lane = t & 31, wid = t >> 5;

    sflags[t] = 0u;
    __syncthreads();

    long long m[9] = {0,0,0,0,0,0,0,0,0};
    for (int i = t; i < NV; i += 256) {
        int4 p = ((const int4*)idx)[i];
        int key = ((p.x * 32 + (p.y >> 2)) * 32 + (p.z >> 2)) * 4 + (p.w >> 2);
        skeys[i] = (unsigned short)key;
        atomicOr(&sflags[key >> 5], 1u << (key & 31));
        g_map[((p.x * GXD + p.y) * GYD + p.z) * GZD + p.w] = i + 1;
        long long xs = p.y, ys = p.z, zs = p.w;
        m[0]+=xs; m[1]+=ys; m[2]+=zs; m[3]+=xs*xs; m[4]+=ys*ys; m[5]+=zs*zs;
        m[6]+=xs*ys; m[7]+=xs*zs; m[8]+=ys*zs;
    }
    __syncthreads();

    // scan of popcounts
    unsigned w = sflags[t];
    int cnt = __popc(w);
    sscan[t] = cnt; __syncthreads();
    for (int off = 1; off < 256; off <<= 1) {
        int v = (t >= off) ? sscan[t - off] : 0;
        __syncthreads(); sscan[t] += v; __syncthreads();
    }
    int excl = sscan[t] - cnt;
    srank[t] = excl;
    unsigned wb = w;
    while (wb) {
        int bit = __ffs(wb) - 1; wb &= wb - 1;
        int rank = excl + __popc(w & ((1u << bit) - 1u));
        int key = t * 32 + bit;
        int4 u;
        u.w = key & 3; u.z = (key >> 2) & 31; u.y = (key >> 7) & 31; u.x = key >> 12;
        g_unq[rank] = u;
    }
    __syncthreads();

    // inverse map per voxel
    for (int i = t; i < NV; i += 256) {
        int key = skeys[i];
        g_sinv[i] = srank[key >> 5] + __popc(sflags[key >> 5] & ((1u << (key & 31)) - 1u));
    }

    // moment reductions (indices)
    for (int k = 0; k < 9; k++) {
        long long v = m[k];
        for (int o = 16; o; o >>= 1) v += __shfl_xor_sync(~0u, v, o);
        if (lane == 0) wred[wid] = v;
        __syncthreads();
        if (t == 0) { long long s = 0; for (int i = 0; i < 8; i++) s += wred[i]; Si[k] = (double)s; }
        __syncthreads();
    }
    // moments (unique supervoxels)
    {
        int4 u = g_unq[t];
        long long xs = u.y, ys = u.z, zs = u.w;
        long long mu9[9] = { xs, ys, zs, xs*xs, ys*ys, zs*zs, xs*ys, xs*zs, ys*zs };
        for (int k = 0; k < 9; k++) {
            long long v = mu9[k];
            for (int o = 16; o; o >>= 1) v += __shfl_xor_sync(~0u, v, o);
            if (lane == 0) wred[wid] = v;
            __syncthreads();
            if (t == 0) { long long s = 0; for (int i = 0; i < 8; i++) s += wred[i]; Su[k] = (double)s; }
            __syncthreads();
        }
    }
    // closed-form BN fold for pairwise pos-bias MLP
    if (t == 0) {
        double mi[3], mu_[3];
        for (int a = 0; a < 3; a++) {
            mi[a]  = Si[a] / (double)NV;
            mu_[a] = Su[a] / (double)NSV;
            md[a]  = mi[a] - mu_[a];
        }
        const int pid[3][3] = { {3,6,7}, {6,4,8}, {7,8,5} };
        for (int a = 0; a < 3; a++)
            for (int b = 0; b < 3; b++)
                Cv[a][b] = (Si[pid[a][b]] / (double)NV  - mi[a]  * mi[b])
                         + (Su[pid[a][b]] / (double)NSV - mu_[a] * mu_[b]);
    }
    __syncthreads();
    if (t < 64) {
        int j = t;
        double w3[3];
        for (int a = 0; a < 3; a++) w3[a] = (double)pw1[a*64 + j];
        double mu = md[0]*w3[0] + md[1]*w3[1] + md[2]*w3[2] + (double)pb1[j];
        double var = 0.0;
        for (int a = 0; a < 3; a++)
            for (int b = 0; b < 3; b++)
                var += w3[a] * Cv[a][b] * w3[b];
        float s = rsqrtf((float)var + EPSF) * pg1[j];
        for (int a = 0; a < 3; a++) g_pweff[a*64 + j] = (float)w3[a] * s;
        g_pweff[192 + j] = (float)((double)pb1[j] - mu) * s + pbe1[j];
    }
}

// ================= per-voxel softmax + scatter =============================
__global__ void k_sms(const float* __restrict__ feat) {
    int n = blockIdx.x, t = threadIdx.x;
    float v = feat[n*CC + t];
    __shared__ float redm[4], reds[4];
    float m = v;
    for (int o = 16; o; o >>= 1) m = fmaxf(m, __shfl_xor_sync(~0u, m, o));
    if ((t & 31) == 0) redm[t >> 5] = m;
    __syncthreads();
    m = fmaxf(fmaxf(redm[0], redm[1]), fmaxf(redm[2], redm[3]));
    float e = __expf(v - m);
    float s = e;
    for (int o = 16; o; o >>= 1) s += __shfl_xor_sync(~0u, s, o);
    if ((t & 31) == 0) reds[t >> 5] = s;
    __syncthreads();
    s = reds[0] + reds[1] + reds[2] + reds[3];
    atomicAdd(&g_acc.cf[g_sinv[n]*CC + t], e / s);
}

// ================= gemm1 (cf@cw1+cb1) + BN stat atomics ====================
__global__ void k_gemm1(const float* __restrict__ cw1, const float* __restrict__ cb1) {
    __shared__ float srT[CC*4];
    int t = threadIdx.x, r0 = blockIdx.x * 4;
    for (int rr = 0; rr < 4; rr++) srT[t*4 + rr] = g_acc.cf[(r0+rr)*CC + t];
    __syncthreads();
    float b = cb1[t];
    ull a0 = pk(b, b), a1 = pk(b, b);
    #pragma unroll 8
    for (int k = 0; k < CC; k++) {
        float wv = cw1[k*CC + t];
        ull w2 = pk(wv, wv);
        FMA2(a0, pk2(*(const float2*)&srT[k*4]),     w2, a0);
        FMA2(a1, pk2(*(const float2*)&srT[k*4 + 2]), w2, a1);
    }
    float v0, v1, v2, v3;
    upk(v0, v1, a0); upk(v2, v3, a1);
    g_hid[(r0+0)*CC + t] = v0; g_hid[(r0+1)*CC + t] = v1;
    g_hid[(r0+2)*CC + t] = v2; g_hid[(r0+3)*CC + t] = v3;
    atomicAdd(&g_acc.s1[t], v0 + v1 + v2 + v3);
    atomicAdd(&g_acc.s2[t], v0*v0 + v1*v1 + v2*v2 + v3*v3);
}

// ================= BN+ReLU + gemm2 + K/V projections =======================
__global__ void k_gemm2kv(const float* __restrict__ cw2, const float* __restrict__ cb2,
                          const float* __restrict__ cg1, const float* __restrict__ cbe1,
                          const float* __restrict__ wk,  const float* __restrict__ bk,
                          const float* __restrict__ wv,  const float* __restrict__ bv) {
    __shared__ float actT[CC*4], hT[CC*4];
    int t = threadIdx.x, r0 = blockIdx.x * 4;
    float mu  = g_acc.s1[t] * (1.f/NSV);
    float var = g_acc.s2[t] * (1.f/NSV) - mu * mu;
    float A = cg1[t] * rsqrtf(var + EPSF);
    float D = cbe1[t] - mu * A;
    for (int rr = 0; rr < 4; rr++)
        actT[t*4 + rr] = fmaxf(fmaf(g_hid[(r0+rr)*CC + t], A, D), 0.f);
    __syncthreads();
    {
        float b = cb2[t];
        ull a0 = pk(b, b), a1 = pk(b, b);
        #pragma unroll 8
        for (int k = 0; k < CC; k++) {
            float wvv = cw2[k*CC + t];
            ull w2 = pk(wvv, wvv);
            FMA2(a0, pk2(*(const float2*)&actT[k*4]),     w2, a0);
            FMA2(a1, pk2(*(const float2*)&actT[k*4 + 2]), w2, a1);
        }
        float v0, v1, v2, v3;
        upk(v0, v1, a0); upk(v2, v3, a1);
        hT[t*4+0] = v0; hT[t*4+1] = v1; hT[t*4+2] = v2; hT[t*4+3] = v3;
    }
    __syncthreads();
    {
        float bkt = bk[t], bvt = bv[t];
        ull k0 = pk(bkt, bkt), k1 = pk(bkt, bkt);
        ull u0 = pk(bvt, bvt), u1 = pk(bvt, bvt);
        #pragma unroll 4
        for (int k = 0; k < CC; k++) {
            ull f0 = pk2(*(const float2*)&hT[k*4]);
            ull f1 = pk2(*(const float2*)&hT[k*4 + 2]);
            float a = wk[k*CC + t], b = wv[k*CC + t];
            ull wa = pk(a, a), wb = pk(b, b);
            FMA2(k0, f0, wa, k0); FMA2(k1, f1, wa, k1);
            FMA2(u0, f0, wb, u0); FMA2(u1, f1, wb, u1);
        }
        float x0,x1,x2,x3, y0,y1,y2,y3;
        upk(x0,x1,k0); upk(x2,x3,k1); upk(y0,y1,u0); upk(y2,y3,u1);
        g_kT[t*NSV + r0+0] = x0; g_kT[t*NSV + r0+1] = x1;
        g_kT[t*NSV + r0+2] = x2; g_kT[t*NSV + r0+3] = x3;
        g_v[(r0+0)*CC + t] = y0; g_v[(r0+1)*CC + t] = y1;
        g_v[(r0+2)*CC + t] = y2; g_v[(r0+3)*CC + t] = y3;
    }
}

// ================= fully fused attention (packed f32x2) ====================
__global__ void __launch_bounds__(256, 2)
k_attn(const int* __restrict__ idx, const float* __restrict__ feat,
       const float* __restrict__ wq, const float* __restrict__ bq,
       const float* __restrict__ wo, const float* __restrict__ bo,
       const float* __restrict__ lng, const float* __restrict__ lnb,
       const float* __restrict__ pw2, const float* __restrict__ pb2) {
    extern __shared__ float sm[];
    float* sfeatT = sm;                    // [k][g]   1024
    float* sqT    = sfeatT + CC*GQ;        // [c][g]   1024
    float* satt   = sqT + CC*GQ;           // [h][s][g] 16384
    float* sctxT  = satt + NH*NSV*GQ;      // [k][g]   1024
    float* st     = sctxT + CC*GQ;         // [j][g]   512
    float* sw     = st + 64*GQ;            // 256
    float* spw2   = sw + 256;              // 64
    float* sred   = spw2 + 64;             // 64
    float* spos   = sred + 64;             // 24

    int t = threadIdx.x;
    int n0 = blockIdx.x * GQ;
    int c = t & (CC-1), grp = t >> 7, g0 = grp * 4;

    sw[t] = g_pweff[t];
    if (t < 64) spw2[t] = pw2[t];
    if (t < GQ*3) spos[t] = (float)idx[(n0 + t/3)*4 + 1 + (t%3)];
    #pragma unroll
    for (int i = 0; i < GQ*CC/256; i++) {
        int li = t + 256*i;
        sfeatT[(li & (CC-1))*GQ + (li >> 7)] = feat[n0*CC + li];
    }
    __syncthreads();

    // t_j(g) for pbias
    for (int p = t; p < 64*GQ; p += 256) {
        int j = p >> 3, g = p & 7;
        st[p] = fmaf(spos[g*3], sw[j],
                fmaf(spos[g*3+1], sw[64+j],
                fmaf(spos[g*3+2], sw[128+j], sw[192+j])));
    }

    // ---- q projection ----
    {
        float b = bq[c];
        ull a0 = pk(b, b), a1 = pk(b, b);
        #pragma unroll 4
        for (int k = 0; k < CC; k++) {
            float w = wq[k*CC + c];
            ull w2 = pk(w, w);
            FMA2(a0, pk2(*(const float2*)&sfeatT[k*GQ + g0]),     w2, a0);
            FMA2(a1, pk2(*(const float2*)&sfeatT[k*GQ + g0 + 2]), w2, a1);
        }
        float q0,q1,q2,q3;
        upk(q0,q1,a0); upk(q2,q3,a1);
        sqT[c*GQ + g0+0] = q0*0.25f; sqT[c*GQ + g0+1] = q1*0.25f;
        sqT[c*GQ + g0+2] = q2*0.25f; sqT[c*GQ + g0+3] = q3*0.25f;
    }
    __syncthreads();

    // ---- pbias (factorized, BN folded): thread = super-voxel s ----
    float pb[GQ];
    {
        int4 u = g_unq[t];
        float ux = (float)u.y, uy = (float)u.z, uz = (float)u.w;
        float pbv = pb2[0];
        #pragma unroll
        for (int g = 0; g < GQ; g++) pb[g] = pbv;
        #pragma unroll 2
        for (int j = 0; j < 64; j++) {
            float uj = fmaf(ux, sw[j], fmaf(uy, sw[64+j], uz * sw[128+j]));
            float w2j = spw2[j];
            float4 tA = *(const float4*)&st[j*GQ];
            float4 tB = *(const float4*)&st[j*GQ + 4];
            pb[0] = fmaf(fmaxf(tA.x - uj, 0.f), w2j, pb[0]);
            pb[1] = fmaf(fmaxf(tA.y - uj, 0.f), w2j, pb[1]);
            pb[2] = fmaf(fmaxf(tA.z - uj, 0.f), w2j, pb[2]);
            pb[3] = fmaf(fmaxf(tA.w - uj, 0.f), w2j, pb[3]);
            pb[4] = fmaf(fmaxf(tB.x - uj, 0.f), w2j, pb[4]);
            pb[5] = fmaf(fmaxf(tB.y - uj, 0.f), w2j, pb[5]);
            pb[6] = fmaf(fmaxf(tB.z - uj, 0.f), w2j, pb[6]);
            pb[7] = fmaf(fmaxf(tB.w - uj, 0.f), w2j, pb[7]);
        }
    }
    // ---- scores per head ----
    {
        ull pbp0 = pk(pb[0],pb[1]), pbp1 = pk(pb[2],pb[3]);
        ull pbp2 = pk(pb[4],pb[5]), pbp3 = pk(pb[6],pb[7]);
        for (int h = 0; h < NH; h++) {
            ull a0 = pbp0, a1 = pbp1, a2 = pbp2, a3 = pbp3;
            #pragma unroll
            for (int c16 = 0; c16 < DHD; c16++) {
                int cc = h*DHD + c16;
                float kv = g_kT[cc*NSV + t];
                ull kv2 = pk(kv, kv);
                FMA2(a0, pk2(*(const float2*)&sqT[cc*GQ + 0]), kv2, a0);
                FMA2(a1, pk2(*(const float2*)&sqT[cc*GQ + 2]), kv2, a1);
                FMA2(a2, pk2(*(const float2*)&sqT[cc*GQ + 4]), kv2, a2);
                FMA2(a3, pk2(*(const float2*)&sqT[cc*GQ + 6]), kv2, a3);
            }
            ull* dst = (ull*)&satt[(h*NSV + t)*GQ];
            dst[0] = a0; dst[1] = a1; dst[2] = a2; dst[3] = a3;
        }
    }
    __syncthreads();

    // ---- softmax over s for each (h,g) ----
    {
        int warp = t >> 5, lane = t & 31;
        for (int p = warp; p < GQ*NH; p += 8) {
            int h = p >> 3, g = p & 7;
            float* row = satt + h*NSV*GQ + g;
            float vals[8];
            float m = -1e30f;
            #pragma unroll
            for (int k = 0; k < 8; k++) { vals[k] = row[(lane + 32*k)*GQ]; m = fmaxf(m, vals[k]); }
            for (int o = 16; o; o >>= 1) m = fmaxf(m, __shfl_xor_sync(~0u, m, o));
            float sum = 0.f;
            #pragma unroll
            for (int k = 0; k < 8; k++) { vals[k] = __expf(vals[k] - m); sum += vals[k]; }
            for (int o = 16; o; o >>= 1) sum += __shfl_xor_sync(~0u, sum, o);
            float inv = 1.f / sum;
            #pragma unroll
            for (int k = 0; k < 8; k++) row[(lane + 32*k)*GQ] = vals[k] * inv;
        }
    }
    __syncthreads();

    // ---- attn @ V ----
    {
        int hh = c >> 4;
        ull a0 = 0ull, a1 = 0ull;
        const float* abase = satt + hh*NSV*GQ + g0;
        #pragma unroll 4
        for (int s = 0; s < NSV; s++) {
            float vv = g_v[s*CC + c];
            ull v2 = pk(vv, vv);
            FMA2(a0, pk2(*(const float2*)&abase[s*GQ]),     v2, a0);
            FMA2(a1, pk2(*(const float2*)&abase[s*GQ + 2]), v2, a1);
        }
        float x0,x1,x2,x3;
        upk(x0,x1,a0); upk(x2,x3,a1);
        sctxT[c*GQ + g0+0] = x0; sctxT[c*GQ + g0+1] = x1;
        sctxT[c*GQ + g0+2] = x2; sctxT[c*GQ + g0+3] = x3;
    }
    __syncthreads();

    // ---- o-proj + residual + LayerNorm ----
    {
        float b = bo[c];
        ull a0 = pk(b, b), a1 = pk(b, b);
        #pragma unroll 4
        for (int k = 0; k < CC; k++) {
            float w = wo[k*CC + c];
            ull w2 = pk(w, w);
            FMA2(a0, pk2(*(const float2*)&sctxT[k*GQ + g0]),     w2, a0);
            FMA2(a1, pk2(*(const float2*)&sctxT[k*GQ + g0 + 2]), w2, a1);
        }
        float o0,o1,o2,o3;
        upk(o0,o1,a0); upk(o2,o3,a1);
        float yv[4];
        yv[0] = sfeatT[c*GQ + g0+0] + o0;
        yv[1] = sfeatT[c*GQ + g0+1] + o1;
        yv[2] = sfeatT[c*GQ + g0+2] + o2;
        yv[3] = sfeatT[c*GQ + g0+3] + o3;

        int warp = t >> 5, lane = t & 31, w4 = warp & 3;
        #pragma unroll
        for (int gg = 0; gg < 4; gg++) {
            float s = yv[gg], ss = yv[gg]*yv[gg];
            for (int o = 16; o; o >>= 1) {
                s  += __shfl_xor_sync(~0u, s, o);
                ss += __shfl_xor_sync(~0u, ss, o);
            }
            if (lane == 0) {
                sred[(g0+gg)*4 + w4]      = s;
                sred[32 + (g0+gg)*4 + w4] = ss;
            }
        }
        __syncthreads();
        float lg = lng[c], lb = lnb[c];
        #pragma unroll
        for (int gg = 0; gg < 4; gg++) {
            int g = g0 + gg;
            float s  = sred[g*4+0] + sred[g*4+1] + sred[g*4+2] + sred[g*4+3];
            float ss = sred[32+g*4+0] + sred[32+g*4+1] + sred[32+g*4+2] + sred[32+g*4+3];
            float mu = s * (1.f/CC), var = ss * (1.f/CC) - mu*mu;
            g_y[(n0+g)*CC + c] = (yv[gg] - mu) * rsqrtf(var + EPSF) * lg + lb;
        }
    }
}

// ================= submanifold 3^3 conv (packed oc pairs) ==================
__global__ void __launch_bounds__(320, 2)
k_conv(const int* __restrict__ idx, const float* __restrict__ segw,
       const float* __restrict__ segb, float* __restrict__ out) {
    __shared__ float sW[CC*NCL];
    __shared__ int4 svox[32];
    int t = threadIdx.x;
    int n0 = blockIdx.x * 32;
    if (t < 32) svox[t] = ((const int4*)idx)[n0 + t];
    __syncthreads();
    int v = t / 10, op = t - v * 10;     // 32 voxels x 10 oc-pairs
    int4 pv = svox[v];
    float2 bb = *(const float2*)&segb[op*2];
    ull acc0 = pk(bb.x, bb.y), acc1 = 0ull;
    for (int d = 0; d < 27; d++) {
        for (int i = t; i < CC*NCL; i += 320) sW[i] = segw[d*CC*NCL + i];
        __syncthreads();
        int ax = d / 9, ay = (d / 3) % 3, az = d % 3;
        int x = pv.y + ax - 1, y = pv.z + ay - 1, z = pv.w + az - 1;
        if (x >= 0 && x < GXD && y >= 0 && y < GYD && z >= 0 && z < GZD) {
            int m = g_map[((pv.x * GXD + x) * GYD + y) * GZD + z];
            if (m > 0) {
                const float* yr = &g_y[(m-1)*CC];
                #pragma unroll 8
                for (int c2 = 0; c2 < CC; c2 += 2) {
                    float y0 = yr[c2], y1 = yr[c2+1];
                    FMA2(acc0, pk(y0, y0), pk2(*(const float2*)&sW[c2*NCL + op*2]),     acc0);
                    FMA2(acc1, pk(y1, y1), pk2(*(const float2*)&sW[(c2+1)*NCL + op*2]), acc1);
                }
            }
        }
        __syncthreads();
    }
    float a0, a1, b0, b1;
    upk(a0, a1, acc0); upk(b0, b1, acc1);
    float2 res; res.x = a0 + b0; res.y = a1 + b1;
    *(float2*)&out[(n0 + v)*NCL + op*2] = res;
}

// --------------------------------------------------------------------------
extern "C" void kernel_launch(void* const* d_in, const int* in_sizes, int n_in,
                              void* d_out, int out_size) {
    const int*   idx  = (const int*)  d_in[0];
    const float* feat = (const float*)d_in[1];
    const float* cw1  = (const float*)d_in[2];
    const float* cb1  = (const float*)d_in[3];
    const float* cg1  = (const float*)d_in[4];
    const float* cbe1 = (const float*)d_in[5];
    const float* cw2  = (const float*)d_in[6];
    const float* cb2  = (const float*)d_in[7];
    const float* pw1  = (const float*)d_in[8];
    const float* pb1  = (const float*)d_in[9];
    const float* pg1  = (const float*)d_in[10];
    const float* pbe1 = (const float*)d_in[11];
    const float* pw2  = (const float*)d_in[12];
    const float* pb2  = (const float*)d_in[13];
    const float* wq   = (const float*)d_in[14];
    const float* bq   = (const float*)d_in[15];
    const float* wk   = (const float*)d_in[16];
    const float* bk   = (const float*)d_in[17];
    const float* wv   = (const float*)d_in[18];
    const float* bv   = (const float*)d_in[19];
    const float* wo   = (const float*)d_in[20];
    const float* bo   = (const float*)d_in[21];
    const float* ln_g = (const float*)d_in[22];
    const float* ln_b = (const float*)d_in[23];
    const float* segw = (const float*)d_in[24];
    const float* segb = (const float*)d_in[25];

    void* p_acc;
    cudaGetSymbolAddress(&p_acc, g_acc);

    constexpr int ATTN_SMEM = (CC*GQ*3 + NH*NSV*GQ + 64*GQ + 256 + 64 + 64 + 24 + 8) * 4;
    cudaFuncSetAttribute(k_attn, cudaFuncAttributeMaxDynamicSharedMemorySize, ATTN_SMEM);

    cudaMemsetAsync(p_acc, 0, sizeof(Acc), 0);

    k_prep    <<<1, 256>>>(idx, pw1, pb1, pg1, pbe1);
    k_sms     <<<NV, 128>>>(feat);
    k_gemm1   <<<NSV/4, 128>>>(cw1, cb1);
    k_gemm2kv <<<NSV/4, 128>>>(cw2, cb2, cg1, cbe1, wk, bk, wv, bv);
    k_attn    <<<NV/GQ, 256, ATTN_SMEM>>>(idx, feat, wq, bq, wo, bo, ln_g, ln_b, pw2, pb2);
    k_conv    <<<NV/32, 320>>>(idx, segw, segb, (float*)d_out);
}